// round 2
// baseline (speedup 1.0000x reference)
#include <cuda_runtime.h>
#include <math.h>

#define D    1024
#define E    8
#define HID  4096
#define NMAX 2048

// Scratch (device globals -- allowed; no runtime allocation)
__device__ float g_H[2 * NMAX * HID];   // packed rows across experts: 4096 x 4096
__device__ float g_Y[2 * NMAX * D];     // 4096 x 1024
__device__ int   g_cnt[E];
__device__ int   g_offs[E];
__device__ int   g_list[E * NMAX];
__device__ int   g_tok_e[2 * NMAX];
__device__ int   g_tok_p[2 * NMAX];
__device__ float g_tok_w[2 * NMAX];
__device__ float g_imp[E];
__device__ float g_lse2;

__device__ __forceinline__ float gelu_tanh(float v) {
    const float c = 0.7978845608028654f;
    float t = tanhf(c * (v + 0.044715f * v * v * v));
    return 0.5f * v * (1.0f + t);
}

__global__ void init_kernel() {
    int i = threadIdx.x;
    if (i < E) { g_cnt[i] = 0; g_imp[i] = 0.0f; }
    if (i == 0) g_lse2 = 0.0f;
}

// One warp per token: logits, softmax, top-2, aux stats, expert list append.
__global__ void router_kernel(const float* __restrict__ x,
                              const float* __restrict__ Wr,
                              const float* __restrict__ br, int N) {
    int gwarp = (blockIdx.x * blockDim.x + threadIdx.x) >> 5;
    int lane  = threadIdx.x & 31;
    if (gwarp >= N) return;
    int t = gwarp;
    const float* xr = x + (size_t)t * D;

    float acc[E];
#pragma unroll
    for (int e = 0; e < E; e++) acc[e] = 0.0f;

    for (int d = lane; d < D; d += 32) {
        float xv = xr[d];
        const float4* w4 = (const float4*)(Wr + (size_t)d * E);
        float4 wa = w4[0], wb = w4[1];
        acc[0] += xv * wa.x; acc[1] += xv * wa.y;
        acc[2] += xv * wa.z; acc[3] += xv * wa.w;
        acc[4] += xv * wb.x; acc[5] += xv * wb.y;
        acc[6] += xv * wb.z; acc[7] += xv * wb.w;
    }
#pragma unroll
    for (int e = 0; e < E; e++) {
#pragma unroll
        for (int off = 16; off; off >>= 1)
            acc[e] += __shfl_down_sync(0xffffffffu, acc[e], off);
    }

    if (lane == 0) {
        float l[E];
#pragma unroll
        for (int e = 0; e < E; e++) l[e] = acc[e] + br[e];
        float m = l[0];
#pragma unroll
        for (int e = 1; e < E; e++) m = fmaxf(m, l[e]);
        float p[E];
        float s = 0.0f;
#pragma unroll
        for (int e = 0; e < E; e++) { p[e] = expf(l[e] - m); s += p[e]; }
        float inv = 1.0f / s;
        float lse = m + logf(s);
        atomicAdd(&g_lse2, lse * lse);

        int i0 = 0, i1 = 0;
        float p0 = -1.0f, p1 = -1.0f;
#pragma unroll
        for (int e = 0; e < E; e++) {
            float pe = p[e] * inv;
            atomicAdd(&g_imp[e], pe);
            if (pe > p0)      { p1 = p0; i1 = i0; p0 = pe; i0 = e; }
            else if (pe > p1) { p1 = pe; i1 = e; }
        }
        float wsum = p0 + p1 + 1e-12f;
        float w0 = p0 / wsum, w1 = p1 / wsum;

        int pos0 = atomicAdd(&g_cnt[i0], 1);
        int pos1 = atomicAdd(&g_cnt[i1], 1);
        g_list[i0 * NMAX + pos0] = t;
        g_list[i1 * NMAX + pos1] = t;
        int t2 = t * 2;
        g_tok_e[t2]     = i0; g_tok_p[t2]     = pos0; g_tok_w[t2]     = w0;
        g_tok_e[t2 + 1] = i1; g_tok_p[t2 + 1] = pos1; g_tok_w[t2 + 1] = w1;
    }
}

__global__ void scan_kernel() {
    if (threadIdx.x == 0) {
        int o = 0;
        for (int e = 0; e < E; e++) { g_offs[e] = o; o += g_cnt[e]; }
    }
}

// GEMM1: X_gathered[n_e,1024] @ W1[e][1024,4096] + b1 -> gelu -> g_H (packed)
__global__ __launch_bounds__(256) void ffn1_kernel(const float* __restrict__ x,
                                                   const float* __restrict__ W1,
                                                   const float* __restrict__ b1) {
    int e = blockIdx.z;
    int n = g_cnt[e];
    int r0 = blockIdx.y * 64;
    if (r0 >= n) return;
    int c0 = blockIdx.x * 64;

    __shared__ float As[16][68];   // [k][row]
    __shared__ float Bs[16][68];   // [k][col]

    int tid = threadIdx.x;
    int tx = tid & 15, ty = tid >> 4;

    float acc[4][4];
#pragma unroll
    for (int i = 0; i < 4; i++)
#pragma unroll
        for (int j = 0; j < 4; j++) acc[i][j] = 0.0f;

    int ar = tid >> 2;            // row 0..63
    int ak = (tid & 3) * 4;       // k sub-offset 0,4,8,12
    int rowa = r0 + ar;
    const float* xrow = (rowa < n) ? (x + (size_t)g_list[e * NMAX + rowa] * D) : (const float*)0;
    const float* Bbase = W1 + (size_t)e * D * HID + c0;

    for (int k0 = 0; k0 < D; k0 += 16) {
        float4 av = make_float4(0.f, 0.f, 0.f, 0.f);
        if (xrow) av = *(const float4*)(xrow + k0 + ak);
        As[ak + 0][ar] = av.x; As[ak + 1][ar] = av.y;
        As[ak + 2][ar] = av.z; As[ak + 3][ar] = av.w;
#pragma unroll
        for (int i = 0; i < 4; i++) {
            int idx = tid + 256 * i;
            int kk = idx >> 6, c = idx & 63;
            Bs[kk][c] = Bbase[(size_t)(k0 + kk) * HID + c];
        }
        __syncthreads();
#pragma unroll
        for (int kk = 0; kk < 16; kk++) {
            float4 a4 = *(const float4*)&As[kk][ty * 4];
            float4 b4 = *(const float4*)&Bs[kk][tx * 4];
            acc[0][0] += a4.x * b4.x; acc[0][1] += a4.x * b4.y;
            acc[0][2] += a4.x * b4.z; acc[0][3] += a4.x * b4.w;
            acc[1][0] += a4.y * b4.x; acc[1][1] += a4.y * b4.y;
            acc[1][2] += a4.y * b4.z; acc[1][3] += a4.y * b4.w;
            acc[2][0] += a4.z * b4.x; acc[2][1] += a4.z * b4.y;
            acc[2][2] += a4.z * b4.z; acc[2][3] += a4.z * b4.w;
            acc[3][0] += a4.w * b4.x; acc[3][1] += a4.w * b4.y;
            acc[3][2] += a4.w * b4.z; acc[3][3] += a4.w * b4.w;
        }
        __syncthreads();
    }

    int base = g_offs[e];
    const float* bb = b1 + (size_t)e * HID + c0 + tx * 4;
#pragma unroll
    for (int ii = 0; ii < 4; ii++) {
        int r = r0 + ty * 4 + ii;
        if (r < n) {
            float4 o;
            o.x = gelu_tanh(acc[ii][0] + bb[0]);
            o.y = gelu_tanh(acc[ii][1] + bb[1]);
            o.z = gelu_tanh(acc[ii][2] + bb[2]);
            o.w = gelu_tanh(acc[ii][3] + bb[3]);
            *(float4*)(g_H + (size_t)(base + r) * HID + c0 + tx * 4) = o;
        }
    }
}

// GEMM2: g_H[n_e,4096] @ W2[e][4096,1024] + b2 -> g_Y (packed)
__global__ __launch_bounds__(256) void ffn2_kernel(const float* __restrict__ W2,
                                                   const float* __restrict__ b2) {
    int e = blockIdx.z;
    int n = g_cnt[e];
    int r0 = blockIdx.y * 64;
    if (r0 >= n) return;
    int c0 = blockIdx.x * 64;
    int base = g_offs[e];

    __shared__ float As[16][68];
    __shared__ float Bs[16][68];

    int tid = threadIdx.x;
    int tx = tid & 15, ty = tid >> 4;

    float acc[4][4];
#pragma unroll
    for (int i = 0; i < 4; i++)
#pragma unroll
        for (int j = 0; j < 4; j++) acc[i][j] = 0.0f;

    int ar = tid >> 2;
    int ak = (tid & 3) * 4;
    int rowa = r0 + ar;
    const float* arow = (rowa < n) ? (g_H + (size_t)(base + rowa) * HID) : (const float*)0;
    const float* Bbase = W2 + (size_t)e * HID * D + c0;

    for (int k0 = 0; k0 < HID; k0 += 16) {
        float4 av = make_float4(0.f, 0.f, 0.f, 0.f);
        if (arow) av = *(const float4*)(arow + k0 + ak);
        As[ak + 0][ar] = av.x; As[ak + 1][ar] = av.y;
        As[ak + 2][ar] = av.z; As[ak + 3][ar] = av.w;
#pragma unroll
        for (int i = 0; i < 4; i++) {
            int idx = tid + 256 * i;
            int kk = idx >> 6, c = idx & 63;
            Bs[kk][c] = Bbase[(size_t)(k0 + kk) * D + c];
        }
        __syncthreads();
#pragma unroll
        for (int kk = 0; kk < 16; kk++) {
            float4 a4 = *(const float4*)&As[kk][ty * 4];
            float4 b4 = *(const float4*)&Bs[kk][tx * 4];
            acc[0][0] += a4.x * b4.x; acc[0][1] += a4.x * b4.y;
            acc[0][2] += a4.x * b4.z; acc[0][3] += a4.x * b4.w;
            acc[1][0] += a4.y * b4.x; acc[1][1] += a4.y * b4.y;
            acc[1][2] += a4.y * b4.z; acc[1][3] += a4.y * b4.w;
            acc[2][0] += a4.z * b4.x; acc[2][1] += a4.z * b4.y;
            acc[2][2] += a4.z * b4.z; acc[2][3] += a4.z * b4.w;
            acc[3][0] += a4.w * b4.x; acc[3][1] += a4.w * b4.y;
            acc[3][2] += a4.w * b4.z; acc[3][3] += a4.w * b4.w;
        }
        __syncthreads();
    }

    const float* bb = b2 + (size_t)e * D + c0 + tx * 4;
#pragma unroll
    for (int ii = 0; ii < 4; ii++) {
        int r = r0 + ty * 4 + ii;
        if (r < n) {
            float4 o;
            o.x = acc[ii][0] + bb[0];
            o.y = acc[ii][1] + bb[1];
            o.z = acc[ii][2] + bb[2];
            o.w = acc[ii][3] + bb[3];
            *(float4*)(g_Y + (size_t)(base + r) * D + c0 + tx * 4) = o;
        }
    }
}

// out[t] = w0 * Y[row0] + w1 * Y[row1]
__global__ void combine_kernel(float* __restrict__ out) {
    int t = blockIdx.x;
    int t2 = t * 2;
    int e0 = g_tok_e[t2],     e1 = g_tok_e[t2 + 1];
    int r0 = g_offs[e0] + g_tok_p[t2];
    int r1 = g_offs[e1] + g_tok_p[t2 + 1];
    float w0 = g_tok_w[t2], w1 = g_tok_w[t2 + 1];

    int d = threadIdx.x * 4;
    float4 y0 = *(const float4*)(g_Y + (size_t)r0 * D + d);
    float4 y1 = *(const float4*)(g_Y + (size_t)r1 * D + d);
    float4 o;
    o.x = w0 * y0.x + w1 * y1.x;
    o.y = w0 * y0.y + w1 * y1.y;
    o.z = w0 * y0.z + w1 * y1.z;
    o.w = w0 * y0.w + w1 * y1.w;
    *(float4*)(out + (size_t)t * D + d) = o;
}

__global__ void finalize_kernel(float* __restrict__ out, int N, long long out_size) {
    if (threadIdx.x == 0) {
        float invN = 1.0f / (float)N;
        float z = g_lse2 * invN;
        float s = 0.0f;
        for (int e = 0; e < E; e++)
            s += (g_imp[e] * invN) * ((float)g_cnt[e] * invN);
        long long base = (long long)N * D;
        out[base]     = z;
        out[base + 1] = (float)E * s;
        // zero any padding tail
        for (long long i = base + 2; i < out_size; i++) out[i] = 0.0f;
    }
}

extern "C" void kernel_launch(void* const* d_in, const int* in_sizes, int n_in,
                              void* d_out, int out_size) {
    const float* x  = (const float*)d_in[0];
    const float* Wr = (const float*)d_in[1];
    const float* br = (const float*)d_in[2];
    const float* W1 = (const float*)d_in[3];
    const float* b1 = (const float*)d_in[4];
    const float* W2 = (const float*)d_in[5];
    const float* b2 = (const float*)d_in[6];
    float* out = (float*)d_out;

    int N = in_sizes[0] / D;   // 2048

    init_kernel<<<1, 32>>>();
    {
        int warps_per_block = 8;
        int blocks = (N + warps_per_block - 1) / warps_per_block;
        router_kernel<<<blocks, warps_per_block * 32>>>(x, Wr, br, N);
    }
    scan_kernel<<<1, 1>>>();

    {
        dim3 grid(HID / 64, (N + 63) / 64, E);
        ffn1_kernel<<<grid, 256>>>(x, W1, b1);
    }
    {
        dim3 grid(D / 64, (N + 63) / 64, E);
        ffn2_kernel<<<grid, 256>>>(W2, b2);
    }
    combine_kernel<<<N, 256>>>(out);
    finalize_kernel<<<1, 32>>>(out, N, (long long)out_size);
}

// round 8
// speedup vs baseline: 2.4304x; 2.4304x over previous
#include <cuda_runtime.h>
#include <cuda_bf16.h>
#include <math.h>
#include <stdint.h>

#define D    1024
#define E    8
#define HID  4096
#define NMAX 2048

// ---------------- device scratch (static globals: allowed) ----------------
__device__ __nv_bfloat16 g_Xhi[NMAX * D];
__device__ __nv_bfloat16 g_Xlo[NMAX * D];
__device__ __nv_bfloat16 g_W1hi[E * D * HID];
__device__ __nv_bfloat16 g_W1lo[E * D * HID];
__device__ __nv_bfloat16 g_W2hi[E * HID * D];
__device__ __nv_bfloat16 g_W2lo[E * HID * D];
__device__ __nv_bfloat16 g_Hhi[2 * NMAX * HID];
__device__ __nv_bfloat16 g_Hlo[2 * NMAX * HID];
__device__ float g_Y[2 * NMAX * D];
__device__ int   g_cnt[E];
__device__ int   g_offs[E];
__device__ int   g_list[E * NMAX];
__device__ int   g_tok_e[2 * NMAX];
__device__ int   g_tok_p[2 * NMAX];
__device__ float g_tok_w[2 * NMAX];
__device__ float g_imp[E];
__device__ float g_lse2;

// ---------------- helpers ----------------
__device__ __forceinline__ uint32_t smem_u32(const void* p) {
    uint32_t a;
    asm("{ .reg .u64 t; cvta.to.shared.u64 t, %1; cvt.u32.u64 %0, t; }"
        : "=r"(a) : "l"(p));
    return a;
}

__device__ __forceinline__ void cpasync16(uint32_t dst, const void* src, uint32_t bytes) {
    asm volatile("cp.async.cg.shared.global [%0], [%1], 16, %2;"
                 :: "r"(dst), "l"(src), "r"(bytes));
}
#define CP_COMMIT() asm volatile("cp.async.commit_group;")
#define CP_WAIT2()  asm volatile("cp.async.wait_group 2;")

__device__ __forceinline__ void ldsm4(uint32_t* r, uint32_t addr) {
    asm volatile("ldmatrix.sync.aligned.m8n8.x4.shared.b16 {%0,%1,%2,%3}, [%4];"
                 : "=r"(r[0]), "=r"(r[1]), "=r"(r[2]), "=r"(r[3]) : "r"(addr));
}
__device__ __forceinline__ void ldsm4t(uint32_t* r, uint32_t addr) {
    asm volatile("ldmatrix.sync.aligned.m8n8.x4.trans.shared.b16 {%0,%1,%2,%3}, [%4];"
                 : "=r"(r[0]), "=r"(r[1]), "=r"(r[2]), "=r"(r[3]) : "r"(addr));
}
__device__ __forceinline__ void mma_bf16(float* c, const uint32_t* a, const uint32_t* b) {
    asm volatile(
        "mma.sync.aligned.m16n8k16.row.col.f32.bf16.bf16.f32 "
        "{%0,%1,%2,%3}, {%4,%5,%6,%7}, {%8,%9}, {%0,%1,%2,%3};"
        : "+f"(c[0]), "+f"(c[1]), "+f"(c[2]), "+f"(c[3])
        : "r"(a[0]), "r"(a[1]), "r"(a[2]), "r"(a[3]), "r"(b[0]), "r"(b[1]));
}

__device__ __forceinline__ float gelu_tanh(float v) {
    const float c = 0.7978845608028654f;
    float t = tanhf(c * (v + 0.044715f * v * v * v));
    return 0.5f * v * (1.0f + t);
}

__device__ __forceinline__ void split2u(float v0, float v1, uint32_t& hi, uint32_t& lo) {
    __nv_bfloat162 h = __floats2bfloat162_rn(v0, v1);
    float r0 = v0 - __bfloat162float(h.x);
    float r1 = v1 - __bfloat162float(h.y);
    __nv_bfloat162 l = __floats2bfloat162_rn(r0, r1);
    hi = *reinterpret_cast<uint32_t*>(&h);
    lo = *reinterpret_cast<uint32_t*>(&l);
}

// ---------------- presplit kernels ----------------
__global__ void split_x_kernel(const float* __restrict__ x) {
    int i = blockIdx.x * blockDim.x + threadIdx.x;   // over pairs
    if (i < NMAX * D / 2) {
        float2 v = ((const float2*)x)[i];
        uint32_t h, l;
        split2u(v.x, v.y, h, l);
        ((uint32_t*)g_Xhi)[i] = h;
        ((uint32_t*)g_Xlo)[i] = l;
    }
}

__global__ void split_w_kernel(const float* __restrict__ src,
                               __nv_bfloat16* __restrict__ dhi,
                               __nv_bfloat16* __restrict__ dlo, int count4) {
    int i = blockIdx.x * blockDim.x + threadIdx.x;
    if (i >= count4) return;
    float4 v = ((const float4*)src)[i];
    uint2 h, l;
    split2u(v.x, v.y, h.x, l.x);
    split2u(v.z, v.w, h.y, l.y);
    ((uint2*)dhi)[i] = h;
    ((uint2*)dlo)[i] = l;
}

// ---------------- small kernels ----------------
__global__ void init_kernel() {
    int i = threadIdx.x;
    if (i < E) { g_cnt[i] = 0; g_imp[i] = 0.0f; }
    if (i == 0) g_lse2 = 0.0f;
}

__global__ void router_kernel(const float* __restrict__ x,
                              const float* __restrict__ Wr,
                              const float* __restrict__ br, int N) {
    int gwarp = (blockIdx.x * blockDim.x + threadIdx.x) >> 5;
    int lane  = threadIdx.x & 31;
    if (gwarp >= N) return;
    int t = gwarp;
    const float* xr = x + (size_t)t * D;

    float acc[E];
#pragma unroll
    for (int e = 0; e < E; e++) acc[e] = 0.0f;
    for (int d = lane; d < D; d += 32) {
        float xv = xr[d];
        const float4* w4 = (const float4*)(Wr + (size_t)d * E);
        float4 wa = w4[0], wb = w4[1];
        acc[0] += xv * wa.x; acc[1] += xv * wa.y;
        acc[2] += xv * wa.z; acc[3] += xv * wa.w;
        acc[4] += xv * wb.x; acc[5] += xv * wb.y;
        acc[6] += xv * wb.z; acc[7] += xv * wb.w;
    }
#pragma unroll
    for (int e = 0; e < E; e++) {
#pragma unroll
        for (int off = 16; off; off >>= 1)
            acc[e] += __shfl_down_sync(0xffffffffu, acc[e], off);
    }

    if (lane == 0) {
        float l[E];
#pragma unroll
        for (int e = 0; e < E; e++) l[e] = acc[e] + br[e];
        float m = l[0];
#pragma unroll
        for (int e = 1; e < E; e++) m = fmaxf(m, l[e]);
        float p[E]; float s = 0.0f;
#pragma unroll
        for (int e = 0; e < E; e++) { p[e] = expf(l[e] - m); s += p[e]; }
        float inv = 1.0f / s;
        float lse = m + logf(s);
        atomicAdd(&g_lse2, lse * lse);

        int i0 = 0, i1 = 0; float p0 = -1.0f, p1 = -1.0f;
#pragma unroll
        for (int e = 0; e < E; e++) {
            float pe = p[e] * inv;
            atomicAdd(&g_imp[e], pe);
            if (pe > p0)      { p1 = p0; i1 = i0; p0 = pe; i0 = e; }
            else if (pe > p1) { p1 = pe; i1 = e; }
        }
        float wsum = p0 + p1 + 1e-12f;
        float w0 = p0 / wsum, w1 = p1 / wsum;
        int pos0 = atomicAdd(&g_cnt[i0], 1);
        int pos1 = atomicAdd(&g_cnt[i1], 1);
        g_list[i0 * NMAX + pos0] = t;
        g_list[i1 * NMAX + pos1] = t;
        int t2 = t * 2;
        g_tok_e[t2]     = i0; g_tok_p[t2]     = pos0; g_tok_w[t2]     = w0;
        g_tok_e[t2 + 1] = i1; g_tok_p[t2 + 1] = pos1; g_tok_w[t2 + 1] = w1;
    }
}

__global__ void scan_kernel() {
    if (threadIdx.x == 0) {
        int o = 0;
        for (int e = 0; e < E; e++) { g_offs[e] = o; o += g_cnt[e]; }
    }
}

// ---------------- mma.sync GEMM ----------------
// Tile: 128(M) x 128(N), BK=32, split-bf16 (hi/lo), 3-MMA per term-pair.
// 256 threads = 8 warps, warp tile 32x64 (4 warps M x 2 warps N).
// SMEM per stage: Ahi[128][40]b16 | Alo | Bhi[32][136]b16 | Blo
#define A_LD_B   80      // A row pitch bytes (40 bf16)
#define B_LD_B   272     // B row pitch bytes (136 bf16)
#define A_REG_SZ 10240   // 128*80
#define B_REG_SZ 8704    // 32*272
#define STAGE_BYTES (2*A_REG_SZ + 2*B_REG_SZ)   // 37888
#define SMEM_TOTAL  (3 * STAGE_BYTES)           // 113664

template<int PHASE>
__global__ __launch_bounds__(256) void ffn_mma(
    const __nv_bfloat16* __restrict__ Whi,
    const __nv_bfloat16* __restrict__ Wlo,
    const float* __restrict__ bias,
    const float* __restrict__ dummy)
{
    constexpr int KDIM = (PHASE == 1) ? D : HID;
    constexpr int NDIM = (PHASE == 1) ? HID : D;
    constexpr int NCH  = KDIM / 32;

    int e = blockIdx.z;
    int n = g_cnt[e];
    int r0 = blockIdx.y * 128;
    if (r0 >= n) return;
    int c0 = blockIdx.x * 128;
    int base = g_offs[e];

    extern __shared__ char smem[];
    uint32_t sb = smem_u32(smem);
    int t = threadIdx.x;
    int lane = t & 31, wid = t >> 5;

    // ---- per-thread cp.async source/dst setup ----
    // A: rows t>>2 and (t>>2)+64; 8 bf16 (16B) per transfer at col (t&3)*8.
    int arow0 = t >> 2;
    const char* asrc[2][2];   // [hl][rowhalf]
    uint32_t abytes[2];
#pragma unroll
    for (int half = 0; half < 2; half++) {
        int rowg = r0 + arow0 + 64 * half;
        bool valid = rowg < n;
        size_t off;
        if (PHASE == 1) {
            int tok = valid ? g_list[e * NMAX + rowg] : 0;
            off = (size_t)tok * D + (t & 3) * 8;
            asrc[0][half] = (const char*)(g_Xhi + off);
            asrc[1][half] = (const char*)(g_Xlo + off);
        } else {
            int rr = valid ? rowg : 0;
            off = (size_t)(base + rr) * HID + (t & 3) * 8;
            asrc[0][half] = (const char*)(g_Hhi + off);
            asrc[1][half] = (const char*)(g_Hlo + off);
        }
        abytes[half] = valid ? 16u : 0u;
    }
    uint32_t adst0 = (uint32_t)(arow0 * A_LD_B + (t & 3) * 16);
    uint32_t adst1 = adst0 + 64 * A_LD_B;

    // B: k rows t>>4 and (t>>4)+16; 16B at col (t&15)*8.
    int bk0 = t >> 4;
    size_t wbase = (size_t)e * KDIM * NDIM + (size_t)bk0 * NDIM + c0 + (t & 15) * 8;
    const char* bsrc_h0 = (const char*)(Whi + wbase);
    const char* bsrc_h1 = (const char*)(Whi + wbase + (size_t)16 * NDIM);
    const char* bsrc_l0 = (const char*)(Wlo + wbase);
    const char* bsrc_l1 = (const char*)(Wlo + wbase + (size_t)16 * NDIM);
    uint32_t bdst0 = (uint32_t)(bk0 * B_LD_B + (t & 15) * 16);
    uint32_t bdst1 = bdst0 + 16 * B_LD_B;

    // issue one stage of cp.async
    auto issue = [&](int kc, int stage) {
        uint32_t s0 = sb + stage * STAGE_BYTES;
        size_t aoff = (size_t)kc * 64;                 // 32 bf16 per chunk
        size_t boff = (size_t)kc * 32 * NDIM * 2;      // bytes
        cpasync16(s0 + adst0,               asrc[0][0] + aoff, abytes[0]);
        cpasync16(s0 + adst1,               asrc[0][1] + aoff, abytes[1]);
        cpasync16(s0 + A_REG_SZ + adst0,    asrc[1][0] + aoff, abytes[0]);
        cpasync16(s0 + A_REG_SZ + adst1,    asrc[1][1] + aoff, abytes[1]);
        uint32_t bb = s0 + 2 * A_REG_SZ;
        cpasync16(bb + bdst0,              bsrc_h0 + boff, 16);
        cpasync16(bb + bdst1,              bsrc_h1 + boff, 16);
        cpasync16(bb + B_REG_SZ + bdst0,   bsrc_l0 + boff, 16);
        cpasync16(bb + B_REG_SZ + bdst1,   bsrc_l1 + boff, 16);
    };

    // ---- per-warp ldmatrix lane offsets ----
    int m0  = (wid & 3) * 32;
    int n0w = (wid >> 2) * 64;
    uint32_t a_lane = (uint32_t)((m0 + (lane & 15)) * A_LD_B + (lane >> 4) * 16);
    uint32_t b_lane = (uint32_t)(((lane & 7) + 8 * ((lane >> 3) & 1)) * B_LD_B
                                 + (n0w + 8 * (lane >> 4)) * 2);

    float acc[2][8][4];
#pragma unroll
    for (int mt = 0; mt < 2; mt++)
#pragma unroll
        for (int nt = 0; nt < 8; nt++)
#pragma unroll
            for (int q = 0; q < 4; q++) acc[mt][nt][q] = 0.0f;

    // prefetch
    issue(0, 0); CP_COMMIT();
    issue(1, 1); CP_COMMIT();

    for (int kc = 0; kc < NCH; kc++) {
        __syncthreads();                       // all warps done with stage (kc+2)%3
        if (kc + 2 < NCH) { issue(kc + 2, (kc + 2) % 3); }
        CP_COMMIT();                           // keep group count uniform
        CP_WAIT2();                            // stage kc complete
        __syncthreads();

        uint32_t sA = sb + (kc % 3) * STAGE_BYTES;
        uint32_t sB = sA + 2 * A_REG_SZ;

#pragma unroll
        for (int ks = 0; ks < 2; ks++) {       // k sub-steps of 16
            uint32_t af[2][2][4];
            uint32_t bf[2][4][4];
#pragma unroll
            for (int hl = 0; hl < 2; hl++)
#pragma unroll
                for (int mt = 0; mt < 2; mt++)
                    ldsm4(af[hl][mt], sA + hl * A_REG_SZ + a_lane
                          + mt * 16 * A_LD_B + ks * 32);
#pragma unroll
            for (int hl = 0; hl < 2; hl++)
#pragma unroll
                for (int g = 0; g < 4; g++)
                    ldsm4t(bf[hl][g], sB + hl * B_REG_SZ + b_lane
                           + ks * 16 * B_LD_B + g * 32);
#pragma unroll
            for (int mt = 0; mt < 2; mt++)
#pragma unroll
                for (int nt = 0; nt < 8; nt++) {
                    const uint32_t* bh = &bf[0][nt >> 1][(nt & 1) * 2];
                    const uint32_t* bl = &bf[1][nt >> 1][(nt & 1) * 2];
                    mma_bf16(acc[mt][nt], af[0][mt], bh);
                    mma_bf16(acc[mt][nt], af[0][mt], bl);
                    mma_bf16(acc[mt][nt], af[1][mt], bh);
                }
        }
    }

    // ---- epilogue ----
    int lr = lane >> 2;
    int lc = (lane & 3) * 2;
#pragma unroll
    for (int mt = 0; mt < 2; mt++) {
#pragma unroll
        for (int nt = 0; nt < 8; nt++) {
            int col = c0 + n0w + nt * 8 + lc;
            float bz0 = bias[e * NDIM + col];
            float bz1 = bias[e * NDIM + col + 1];
            int ra = r0 + m0 + mt * 16 + lr;
            int rb = ra + 8;
            float* a = acc[mt][nt];
            if (PHASE == 1) {
                if (ra < n) {
                    float v0 = gelu_tanh(a[0] + bz0);
                    float v1 = gelu_tanh(a[1] + bz1);
                    uint32_t h, l; split2u(v0, v1, h, l);
                    size_t o = (size_t)(base + ra) * HID + col;
                    *(uint32_t*)(g_Hhi + o) = h;
                    *(uint32_t*)(g_Hlo + o) = l;
                }
                if (rb < n) {
                    float v0 = gelu_tanh(a[2] + bz0);
                    float v1 = gelu_tanh(a[3] + bz1);
                    uint32_t h, l; split2u(v0, v1, h, l);
                    size_t o = (size_t)(base + rb) * HID + col;
                    *(uint32_t*)(g_Hhi + o) = h;
                    *(uint32_t*)(g_Hlo + o) = l;
                }
            } else {
                if (ra < n)
                    *(float2*)(g_Y + (size_t)(base + ra) * D + col)
                        = make_float2(a[0] + bz0, a[1] + bz1);
                if (rb < n)
                    *(float2*)(g_Y + (size_t)(base + rb) * D + col)
                        = make_float2(a[2] + bz0, a[3] + bz1);
            }
        }
    }
    (void)dummy;
}

// ---------------- combine + finalize ----------------
__global__ void combine_kernel(float* __restrict__ out) {
    int t = blockIdx.x;
    int t2 = t * 2;
    int e0 = g_tok_e[t2],     e1 = g_tok_e[t2 + 1];
    int r0 = g_offs[e0] + g_tok_p[t2];
    int r1 = g_offs[e1] + g_tok_p[t2 + 1];
    float w0 = g_tok_w[t2], w1 = g_tok_w[t2 + 1];

    int d = threadIdx.x * 4;
    float4 y0 = *(const float4*)(g_Y + (size_t)r0 * D + d);
    float4 y1 = *(const float4*)(g_Y + (size_t)r1 * D + d);
    float4 o;
    o.x = w0 * y0.x + w1 * y1.x;
    o.y = w0 * y0.y + w1 * y1.y;
    o.z = w0 * y0.z + w1 * y1.z;
    o.w = w0 * y0.w + w1 * y1.w;
    *(float4*)(out + (size_t)t * D + d) = o;
}

__global__ void finalize_kernel(float* __restrict__ out, int N, long long out_size) {
    if (threadIdx.x == 0) {
        float invN = 1.0f / (float)N;
        float z = g_lse2 * invN;
        float s = 0.0f;
        for (int e = 0; e < E; e++)
            s += (g_imp[e] * invN) * ((float)g_cnt[e] * invN);
        long long base = (long long)N * D;
        out[base]     = z;
        out[base + 1] = (float)E * s;
        for (long long i = base + 2; i < out_size; i++) out[i] = 0.0f;
    }
}

extern "C" void kernel_launch(void* const* d_in, const int* in_sizes, int n_in,
                              void* d_out, int out_size) {
    const float* x  = (const float*)d_in[0];
    const float* Wr = (const float*)d_in[1];
    const float* br = (const float*)d_in[2];
    const float* W1 = (const float*)d_in[3];
    const float* b1 = (const float*)d_in[4];
    const float* W2 = (const float*)d_in[5];
    const float* b2 = (const float*)d_in[6];
    float* out = (float*)d_out;

    int N = in_sizes[0] / D;  // 2048

    // symbol addresses for split destinations (no allocation; host-side query)
    void *p_w1hi, *p_w1lo, *p_w2hi, *p_w2lo, *p_whi_s, *p_wlo_s;
    cudaGetSymbolAddress(&p_w1hi, g_W1hi);
    cudaGetSymbolAddress(&p_w1lo, g_W1lo);
    cudaGetSymbolAddress(&p_w2hi, g_W2hi);
    cudaGetSymbolAddress(&p_w2lo, g_W2lo);
    p_whi_s = p_w1hi; p_wlo_s = p_w1lo;

    cudaFuncSetAttribute(ffn_mma<1>, cudaFuncAttributeMaxDynamicSharedMemorySize, SMEM_TOTAL);
    cudaFuncSetAttribute(ffn_mma<2>, cudaFuncAttributeMaxDynamicSharedMemorySize, SMEM_TOTAL);

    init_kernel<<<1, 32>>>();
    {
        int warps_per_block = 8;
        int blocks = (N + warps_per_block - 1) / warps_per_block;
        router_kernel<<<blocks, warps_per_block * 32>>>(x, Wr, br, N);
    }
    scan_kernel<<<1, 1>>>();

    // presplit fp32 -> bf16 hi/lo
    split_x_kernel<<<(NMAX * D / 2 + 255) / 256, 256>>>(x);
    {
        int c4 = E * D * HID / 4;
        split_w_kernel<<<(c4 + 255) / 256, 256>>>(W1, (__nv_bfloat16*)p_w1hi,
                                                  (__nv_bfloat16*)p_w1lo, c4);
        split_w_kernel<<<(c4 + 255) / 256, 256>>>(W2, (__nv_bfloat16*)p_w2hi,
                                                  (__nv_bfloat16*)p_w2lo, c4);
    }

    {
        dim3 grid(HID / 128, NMAX / 128, E);   // 32 x 16 x 8
        ffn_mma<1><<<grid, 256, SMEM_TOTAL>>>((const __nv_bfloat16*)p_w1hi,
                                              (const __nv_bfloat16*)p_w1lo, b1, x);
    }
    {
        dim3 grid(D / 128, NMAX / 128, E);     // 8 x 16 x 8
        ffn_mma<2><<<grid, 256, SMEM_TOTAL>>>((const __nv_bfloat16*)p_w2hi,
                                              (const __nv_bfloat16*)p_w2lo, b2, x);
    }
    combine_kernel<<<N, 256>>>(out);
    finalize_kernel<<<1, 32>>>(out, N, (long long)out_size);
}

// round 10
// speedup vs baseline: 2.8662x; 1.1793x over previous
#include <cuda_runtime.h>
#include <cuda_bf16.h>
#include <math.h>
#include <stdint.h>

#define D    1024
#define E    8
#define HID  4096
#define NMAX 2048

// ---------------- device scratch (static globals: allowed) ----------------
__device__ __nv_bfloat16 g_Xhi[NMAX * D];
__device__ __nv_bfloat16 g_Xlo[NMAX * D];
__device__ __nv_bfloat16 g_W1hi[E * D * HID];
__device__ __nv_bfloat16 g_W1lo[E * D * HID];
__device__ __nv_bfloat16 g_W2hi[E * HID * D];
__device__ __nv_bfloat16 g_W2lo[E * HID * D];
__device__ __nv_bfloat16 g_Hhi[2 * NMAX * HID];
__device__ __nv_bfloat16 g_Hlo[2 * NMAX * HID];
__device__ float g_Y[2 * NMAX * D];
__device__ int   g_cnt[E];
__device__ int   g_offs[E];
__device__ int   g_list[E * NMAX];
__device__ int   g_tok_e[2 * NMAX];
__device__ int   g_tok_p[2 * NMAX];
__device__ float g_tok_w[2 * NMAX];
__device__ float g_imp[E];
__device__ float g_lse2;

// ---------------- helpers ----------------
__device__ __forceinline__ uint32_t smem_u32(const void* p) {
    uint32_t a;
    asm("{ .reg .u64 t; cvta.to.shared.u64 t, %1; cvt.u32.u64 %0, t; }"
        : "=r"(a) : "l"(p));
    return a;
}

__device__ __forceinline__ void cpasync16(uint32_t dst, const void* src, uint32_t bytes) {
    asm volatile("cp.async.cg.shared.global [%0], [%1], 16, %2;"
                 :: "r"(dst), "l"(src), "r"(bytes));
}
#define CP_COMMIT() asm volatile("cp.async.commit_group;")
#define CP_WAIT1()  asm volatile("cp.async.wait_group 1;")

__device__ __forceinline__ void ldsm4(uint32_t* r, uint32_t addr) {
    asm volatile("ldmatrix.sync.aligned.m8n8.x4.shared.b16 {%0,%1,%2,%3}, [%4];"
                 : "=r"(r[0]), "=r"(r[1]), "=r"(r[2]), "=r"(r[3]) : "r"(addr));
}
__device__ __forceinline__ void ldsm4t(uint32_t* r, uint32_t addr) {
    asm volatile("ldmatrix.sync.aligned.m8n8.x4.trans.shared.b16 {%0,%1,%2,%3}, [%4];"
                 : "=r"(r[0]), "=r"(r[1]), "=r"(r[2]), "=r"(r[3]) : "r"(addr));
}
__device__ __forceinline__ void mma_bf16(float* c, const uint32_t* a, const uint32_t* b) {
    asm volatile(
        "mma.sync.aligned.m16n8k16.row.col.f32.bf16.bf16.f32 "
        "{%0,%1,%2,%3}, {%4,%5,%6,%7}, {%8,%9}, {%0,%1,%2,%3};"
        : "+f"(c[0]), "+f"(c[1]), "+f"(c[2]), "+f"(c[3])
        : "r"(a[0]), "r"(a[1]), "r"(a[2]), "r"(a[3]), "r"(b[0]), "r"(b[1]));
}

__device__ __forceinline__ float gelu_tanh(float v) {
    const float c = 0.7978845608028654f;
    float t = tanhf(c * (v + 0.044715f * v * v * v));
    return 0.5f * v * (1.0f + t);
}

__device__ __forceinline__ void split2u(float v0, float v1, uint32_t& hi, uint32_t& lo) {
    __nv_bfloat162 h = __floats2bfloat162_rn(v0, v1);
    float r0 = v0 - __bfloat162float(h.x);
    float r1 = v1 - __bfloat162float(h.y);
    __nv_bfloat162 l = __floats2bfloat162_rn(r0, r1);
    hi = *reinterpret_cast<uint32_t*>(&h);
    lo = *reinterpret_cast<uint32_t*>(&l);
}

// ---------------- fused presplit + init (single launch) ----------------
// work items in float4 granularity: [0, C4W) -> W1, [C4W, 2*C4W) -> W2,
// [2*C4W, 2*C4W + C4X) -> x
#define C4W (E * D * HID / 4)
#define C4X (NMAX * D / 4)

__global__ void split_all_init(const float* __restrict__ W1,
                               const float* __restrict__ W2,
                               const float* __restrict__ x) {
    long long i = (long long)blockIdx.x * blockDim.x + threadIdx.x;
    if (i == 0) {
        g_lse2 = 0.0f;
#pragma unroll
        for (int e = 0; e < E; e++) { g_cnt[e] = 0; g_imp[e] = 0.0f; }
    }
    const float* src;
    __nv_bfloat16 *dhi, *dlo;
    long long j;
    if (i < C4W)                 { src = W1; dhi = g_W1hi; dlo = g_W1lo; j = i; }
    else if (i < 2LL * C4W)      { src = W2; dhi = g_W2hi; dlo = g_W2lo; j = i - C4W; }
    else if (i < 2LL * C4W + C4X){ src = x;  dhi = g_Xhi;  dlo = g_Xlo;  j = i - 2LL * C4W; }
    else return;
    float4 v = ((const float4*)src)[j];
    uint2 h, l;
    split2u(v.x, v.y, h.x, l.x);
    split2u(v.z, v.w, h.y, l.y);
    ((uint2*)dhi)[j] = h;
    ((uint2*)dlo)[j] = l;
}

// ---------------- router ----------------
__global__ void router_kernel(const float* __restrict__ x,
                              const float* __restrict__ Wr,
                              const float* __restrict__ br, int N) {
    int gwarp = (blockIdx.x * blockDim.x + threadIdx.x) >> 5;
    int lane  = threadIdx.x & 31;
    if (gwarp >= N) return;
    int t = gwarp;
    const float* xr = x + (size_t)t * D;

    float acc[E];
#pragma unroll
    for (int e = 0; e < E; e++) acc[e] = 0.0f;
    for (int d = lane; d < D; d += 32) {
        float xv = xr[d];
        const float4* w4 = (const float4*)(Wr + (size_t)d * E);
        float4 wa = w4[0], wb = w4[1];
        acc[0] += xv * wa.x; acc[1] += xv * wa.y;
        acc[2] += xv * wa.z; acc[3] += xv * wa.w;
        acc[4] += xv * wb.x; acc[5] += xv * wb.y;
        acc[6] += xv * wb.z; acc[7] += xv * wb.w;
    }
#pragma unroll
    for (int e = 0; e < E; e++) {
#pragma unroll
        for (int off = 16; off; off >>= 1)
            acc[e] += __shfl_down_sync(0xffffffffu, acc[e], off);
    }

    if (lane == 0) {
        float l[E];
#pragma unroll
        for (int e = 0; e < E; e++) l[e] = acc[e] + br[e];
        float m = l[0];
#pragma unroll
        for (int e = 1; e < E; e++) m = fmaxf(m, l[e]);
        float p[E]; float s = 0.0f;
#pragma unroll
        for (int e = 0; e < E; e++) { p[e] = expf(l[e] - m); s += p[e]; }
        float inv = 1.0f / s;
        float lse = m + logf(s);
        atomicAdd(&g_lse2, lse * lse);

        int i0 = 0, i1 = 0; float p0 = -1.0f, p1 = -1.0f;
#pragma unroll
        for (int e = 0; e < E; e++) {
            float pe = p[e] * inv;
            atomicAdd(&g_imp[e], pe);
            if (pe > p0)      { p1 = p0; i1 = i0; p0 = pe; i0 = e; }
            else if (pe > p1) { p1 = pe; i1 = e; }
        }
        float wsum = p0 + p1 + 1e-12f;
        float w0 = p0 / wsum, w1 = p1 / wsum;
        int pos0 = atomicAdd(&g_cnt[i0], 1);
        int pos1 = atomicAdd(&g_cnt[i1], 1);
        g_list[i0 * NMAX + pos0] = t;
        g_list[i1 * NMAX + pos1] = t;
        int t2 = t * 2;
        g_tok_e[t2]     = i0; g_tok_p[t2]     = pos0; g_tok_w[t2]     = w0;
        g_tok_e[t2 + 1] = i1; g_tok_p[t2 + 1] = pos1; g_tok_w[t2 + 1] = w1;
    }
}

__global__ void scan_kernel() {
    if (threadIdx.x == 0) {
        int o = 0;
        for (int e = 0; e < E; e++) { g_offs[e] = o; o += g_cnt[e]; }
    }
}

// ---------------- mma.sync GEMM ----------------
// Tile: 128(M) x 128(N), BK=32, split-bf16 (hi/lo), 3-MMA per term-pair.
// 256 threads = 8 warps, warp tile 32x64 (4 warps M x 2 warps N).
// 2-stage cp.async pipeline => 75.8 KB smem => 2 CTAs/SM.
#define A_LD_B   80      // A row pitch bytes (40 bf16)
#define B_LD_B   272     // B row pitch bytes (136 bf16)
#define A_REG_SZ 10240   // 128*80
#define B_REG_SZ 8704    // 32*272
#define STAGE_BYTES (2*A_REG_SZ + 2*B_REG_SZ)   // 37888
#define SMEM_TOTAL  (2 * STAGE_BYTES)           // 75776

template<int PHASE>
__global__ __launch_bounds__(256, 2) void ffn_mma(
    const __nv_bfloat16* __restrict__ Whi,
    const __nv_bfloat16* __restrict__ Wlo,
    const float* __restrict__ bias)
{
    constexpr int KDIM = (PHASE == 1) ? D : HID;
    constexpr int NDIM = (PHASE == 1) ? HID : D;
    constexpr int NCH  = KDIM / 32;

    int e = blockIdx.z;
    int n = g_cnt[e];
    int r0 = blockIdx.y * 128;
    if (r0 >= n) return;
    int c0 = blockIdx.x * 128;
    int base = g_offs[e];

    extern __shared__ char smem[];
    uint32_t sb = smem_u32(smem);
    int t = threadIdx.x;
    int lane = t & 31, wid = t >> 5;

    // ---- per-thread cp.async source/dst setup ----
    int arow0 = t >> 2;
    const char* asrc[2][2];   // [hl][rowhalf]
    uint32_t abytes[2];
#pragma unroll
    for (int half = 0; half < 2; half++) {
        int rowg = r0 + arow0 + 64 * half;
        bool valid = rowg < n;
        size_t off;
        if (PHASE == 1) {
            int tok = valid ? g_list[e * NMAX + rowg] : 0;
            off = (size_t)tok * D + (t & 3) * 8;
            asrc[0][half] = (const char*)(g_Xhi + off);
            asrc[1][half] = (const char*)(g_Xlo + off);
        } else {
            int rr = valid ? rowg : 0;
            off = (size_t)(base + rr) * HID + (t & 3) * 8;
            asrc[0][half] = (const char*)(g_Hhi + off);
            asrc[1][half] = (const char*)(g_Hlo + off);
        }
        abytes[half] = valid ? 16u : 0u;
    }
    uint32_t adst0 = (uint32_t)(arow0 * A_LD_B + (t & 3) * 16);
    uint32_t adst1 = adst0 + 64 * A_LD_B;

    int bk0 = t >> 4;
    size_t wbase = (size_t)e * KDIM * NDIM + (size_t)bk0 * NDIM + c0 + (t & 15) * 8;
    const char* bsrc_h0 = (const char*)(Whi + wbase);
    const char* bsrc_h1 = (const char*)(Whi + wbase + (size_t)16 * NDIM);
    const char* bsrc_l0 = (const char*)(Wlo + wbase);
    const char* bsrc_l1 = (const char*)(Wlo + wbase + (size_t)16 * NDIM);
    uint32_t bdst0 = (uint32_t)(bk0 * B_LD_B + (t & 15) * 16);
    uint32_t bdst1 = bdst0 + 16 * B_LD_B;

    auto issue = [&](int kc, int stage) {
        uint32_t s0 = sb + stage * STAGE_BYTES;
        size_t aoff = (size_t)kc * 64;                 // 32 bf16 per chunk
        size_t boff = (size_t)kc * 32 * NDIM * 2;      // bytes
        cpasync16(s0 + adst0,               asrc[0][0] + aoff, abytes[0]);
        cpasync16(s0 + adst1,               asrc[0][1] + aoff, abytes[1]);
        cpasync16(s0 + A_REG_SZ + adst0,    asrc[1][0] + aoff, abytes[0]);
        cpasync16(s0 + A_REG_SZ + adst1,    asrc[1][1] + aoff, abytes[1]);
        uint32_t bb = s0 + 2 * A_REG_SZ;
        cpasync16(bb + bdst0,              bsrc_h0 + boff, 16);
        cpasync16(bb + bdst1,              bsrc_h1 + boff, 16);
        cpasync16(bb + B_REG_SZ + bdst0,   bsrc_l0 + boff, 16);
        cpasync16(bb + B_REG_SZ + bdst1,   bsrc_l1 + boff, 16);
    };

    // ---- per-warp ldmatrix lane offsets ----
    int m0  = (wid & 3) * 32;
    int n0w = (wid >> 2) * 64;
    uint32_t a_lane = (uint32_t)((m0 + (lane & 15)) * A_LD_B + (lane >> 4) * 16);
    uint32_t b_lane = (uint32_t)(((lane & 7) + 8 * ((lane >> 3) & 1)) * B_LD_B
                                 + (n0w + 8 * (lane >> 4)) * 2);

    float acc[2][8][4];
#pragma unroll
    for (int mt = 0; mt < 2; mt++)
#pragma unroll
        for (int nt = 0; nt < 8; nt++)
#pragma unroll
            for (int q = 0; q < 4; q++) acc[mt][nt][q] = 0.0f;

    issue(0, 0); CP_COMMIT();

    for (int kc = 0; kc < NCH; kc++) {
        __syncthreads();                 // all warps done reading stage (kc+1)&1 (from kc-1)
        if (kc + 1 < NCH) issue(kc + 1, (kc + 1) & 1);
        CP_COMMIT();
        CP_WAIT1();                      // stage kc landed (for this thread)
        __syncthreads();                 // visible to all warps

        uint32_t sA = sb + (kc & 1) * STAGE_BYTES;
        uint32_t sB = sA + 2 * A_REG_SZ;

#pragma unroll
        for (int ks = 0; ks < 2; ks++) {       // k sub-steps of 16
            uint32_t af[2][2][4];
#pragma unroll
            for (int hl = 0; hl < 2; hl++)
#pragma unroll
                for (int mt = 0; mt < 2; mt++)
                    ldsm4(af[hl][mt], sA + hl * A_REG_SZ + a_lane
                          + mt * 16 * A_LD_B + ks * 32);
#pragma unroll
            for (int g = 0; g < 4; g++) {      // n groups of 16 cols (2 nt each)
                uint32_t bh[4], bl[4];
                ldsm4t(bh, sB + b_lane + ks * 16 * B_LD_B + g * 32);
                ldsm4t(bl, sB + B_REG_SZ + b_lane + ks * 16 * B_LD_B + g * 32);
#pragma unroll
                for (int mt = 0; mt < 2; mt++) {
#pragma unroll
                    for (int sub = 0; sub < 2; sub++) {
                        float* a = acc[mt][g * 2 + sub];
                        mma_bf16(a, af[0][mt], &bh[sub * 2]);
                        mma_bf16(a, af[0][mt], &bl[sub * 2]);
                        mma_bf16(a, af[1][mt], &bh[sub * 2]);
                    }
                }
            }
        }
    }

    // ---- epilogue ----
    int lr = lane >> 2;
    int lc = (lane & 3) * 2;
#pragma unroll
    for (int mt = 0; mt < 2; mt++) {
#pragma unroll
        for (int nt = 0; nt < 8; nt++) {
            int col = c0 + n0w + nt * 8 + lc;
            float bz0 = bias[e * NDIM + col];
            float bz1 = bias[e * NDIM + col + 1];
            int ra = r0 + m0 + mt * 16 + lr;
            int rb = ra + 8;
            float* a = acc[mt][nt];
            if (PHASE == 1) {
                if (ra < n) {
                    float v0 = gelu_tanh(a[0] + bz0);
                    float v1 = gelu_tanh(a[1] + bz1);
                    uint32_t h, l; split2u(v0, v1, h, l);
                    size_t o = (size_t)(base + ra) * HID + col;
                    *(uint32_t*)(g_Hhi + o) = h;
                    *(uint32_t*)(g_Hlo + o) = l;
                }
                if (rb < n) {
                    float v0 = gelu_tanh(a[2] + bz0);
                    float v1 = gelu_tanh(a[3] + bz1);
                    uint32_t h, l; split2u(v0, v1, h, l);
                    size_t o = (size_t)(base + rb) * HID + col;
                    *(uint32_t*)(g_Hhi + o) = h;
                    *(uint32_t*)(g_Hlo + o) = l;
                }
            } else {
                if (ra < n)
                    *(float2*)(g_Y + (size_t)(base + ra) * D + col)
                        = make_float2(a[0] + bz0, a[1] + bz1);
                if (rb < n)
                    *(float2*)(g_Y + (size_t)(base + rb) * D + col)
                        = make_float2(a[2] + bz0, a[3] + bz1);
            }
        }
    }
}

// ---------------- combine + finalize ----------------
__global__ void combine_kernel(float* __restrict__ out) {
    int t = blockIdx.x;
    int t2 = t * 2;
    int e0 = g_tok_e[t2],     e1 = g_tok_e[t2 + 1];
    int r0 = g_offs[e0] + g_tok_p[t2];
    int r1 = g_offs[e1] + g_tok_p[t2 + 1];
    float w0 = g_tok_w[t2], w1 = g_tok_w[t2 + 1];

    int d = threadIdx.x * 4;
    float4 y0 = *(const float4*)(g_Y + (size_t)r0 * D + d);
    float4 y1 = *(const float4*)(g_Y + (size_t)r1 * D + d);
    float4 o;
    o.x = w0 * y0.x + w1 * y1.x;
    o.y = w0 * y0.y + w1 * y1.y;
    o.z = w0 * y0.z + w1 * y1.z;
    o.w = w0 * y0.w + w1 * y1.w;
    *(float4*)(out + (size_t)t * D + d) = o;
}

__global__ void finalize_kernel(float* __restrict__ out, int N, long long out_size) {
    if (threadIdx.x == 0) {
        float invN = 1.0f / (float)N;
        float z = g_lse2 * invN;
        float s = 0.0f;
        for (int e = 0; e < E; e++)
            s += (g_imp[e] * invN) * ((float)g_cnt[e] * invN);
        long long base = (long long)N * D;
        out[base]     = z;
        out[base + 1] = (float)E * s;
        for (long long i = base + 2; i < out_size; i++) out[i] = 0.0f;
    }
}

extern "C" void kernel_launch(void* const* d_in, const int* in_sizes, int n_in,
                              void* d_out, int out_size) {
    const float* x  = (const float*)d_in[0];
    const float* Wr = (const float*)d_in[1];
    const float* br = (const float*)d_in[2];
    const float* W1 = (const float*)d_in[3];
    const float* b1 = (const float*)d_in[4];
    const float* W2 = (const float*)d_in[5];
    const float* b2 = (const float*)d_in[6];
    float* out = (float*)d_out;

    int N = in_sizes[0] / D;  // 2048

    void *p_w1hi, *p_w1lo, *p_w2hi, *p_w2lo;
    cudaGetSymbolAddress(&p_w1hi, g_W1hi);
    cudaGetSymbolAddress(&p_w1lo, g_W1lo);
    cudaGetSymbolAddress(&p_w2hi, g_W2hi);
    cudaGetSymbolAddress(&p_w2lo, g_W2lo);

    cudaFuncSetAttribute(ffn_mma<1>, cudaFuncAttributeMaxDynamicSharedMemorySize, SMEM_TOTAL);
    cudaFuncSetAttribute(ffn_mma<2>, cudaFuncAttributeMaxDynamicSharedMemorySize, SMEM_TOTAL);

    // launch #1: fused presplit + counter init
    {
        long long items = 2LL * C4W + C4X;
        int blocks = (int)((items + 255) / 256);
        split_all_init<<<blocks, 256>>>(W1, W2, x);
    }
    // launch #2: router
    {
        int warps_per_block = 8;
        int blocks = (N + warps_per_block - 1) / warps_per_block;
        router_kernel<<<blocks, warps_per_block * 32>>>(x, Wr, br, N);
    }
    // launch #3: scan
    scan_kernel<<<1, 1>>>();
    // launch #4: ffn1  (ncu window target)
    {
        dim3 grid(HID / 128, NMAX / 128, E);   // 32 x 16 x 8
        ffn_mma<1><<<grid, 256, SMEM_TOTAL>>>((const __nv_bfloat16*)p_w1hi,
                                              (const __nv_bfloat16*)p_w1lo, b1);
    }
    // launch #5: ffn2
    {
        dim3 grid(D / 128, NMAX / 128, E);     // 8 x 16 x 8
        ffn_mma<2><<<grid, 256, SMEM_TOTAL>>>((const __nv_bfloat16*)p_w2hi,
                                              (const __nv_bfloat16*)p_w2lo, b2);
    }
    combine_kernel<<<N, 256>>>(out);
    finalize_kernel<<<1, 32>>>(out, N, (long long)out_size);
}

// round 11
// speedup vs baseline: 3.1936x; 1.1142x over previous
#include <cuda_runtime.h>
#include <cuda_bf16.h>
#include <math.h>
#include <stdint.h>

#define D    1024
#define E    8
#define HID  4096
#define NMAX 2048

// ---------------- device scratch (static globals: allowed) ----------------
__device__ __nv_bfloat16 g_Xhi[NMAX * D];
__device__ __nv_bfloat16 g_Xlo[NMAX * D];
__device__ __nv_bfloat16 g_W1hi[E * D * HID];
__device__ __nv_bfloat16 g_W1lo[E * D * HID];
__device__ __nv_bfloat16 g_W2hi[E * HID * D];
__device__ __nv_bfloat16 g_W2lo[E * HID * D];
__device__ __nv_bfloat16 g_Hhi[2 * NMAX * HID];
__device__ __nv_bfloat16 g_Hlo[2 * NMAX * HID];
__device__ float g_Y[2 * NMAX * D];
__device__ int   g_cnt[E];
__device__ int   g_offs[E];
__device__ int   g_list[E * NMAX];
__device__ int   g_tok_e[2 * NMAX];
__device__ int   g_tok_p[2 * NMAX];
__device__ float g_tok_w[2 * NMAX];
__device__ float g_imp[E];
__device__ float g_lse2;

// ---------------- helpers ----------------
__device__ __forceinline__ uint32_t smem_u32(const void* p) {
    uint32_t a;
    asm("{ .reg .u64 t; cvta.to.shared.u64 t, %1; cvt.u32.u64 %0, t; }"
        : "=r"(a) : "l"(p));
    return a;
}

__device__ __forceinline__ void cpasync16(uint32_t dst, const void* src, uint32_t bytes) {
    asm volatile("cp.async.cg.shared.global [%0], [%1], 16, %2;"
                 :: "r"(dst), "l"(src), "r"(bytes));
}
#define CP_COMMIT() asm volatile("cp.async.commit_group;")
#define CP_WAITG1() asm volatile("cp.async.wait_group 1;")

__device__ __forceinline__ void ldsm4(uint32_t* r, uint32_t addr) {
    asm volatile("ldmatrix.sync.aligned.m8n8.x4.shared.b16 {%0,%1,%2,%3}, [%4];"
                 : "=r"(r[0]), "=r"(r[1]), "=r"(r[2]), "=r"(r[3]) : "r"(addr));
}
__device__ __forceinline__ void ldsm4t(uint32_t* r, uint32_t addr) {
    asm volatile("ldmatrix.sync.aligned.m8n8.x4.trans.shared.b16 {%0,%1,%2,%3}, [%4];"
                 : "=r"(r[0]), "=r"(r[1]), "=r"(r[2]), "=r"(r[3]) : "r"(addr));
}
__device__ __forceinline__ void mma_bf16(float* c, const uint32_t* a, const uint32_t* b) {
    asm volatile(
        "mma.sync.aligned.m16n8k16.row.col.f32.bf16.bf16.f32 "
        "{%0,%1,%2,%3}, {%4,%5,%6,%7}, {%8,%9}, {%0,%1,%2,%3};"
        : "+f"(c[0]), "+f"(c[1]), "+f"(c[2]), "+f"(c[3])
        : "r"(a[0]), "r"(a[1]), "r"(a[2]), "r"(a[3]), "r"(b[0]), "r"(b[1]));
}

__device__ __forceinline__ float gelu_tanh(float v) {
    const float c = 0.7978845608028654f;
    float t = tanhf(c * (v + 0.044715f * v * v * v));
    return 0.5f * v * (1.0f + t);
}

__device__ __forceinline__ void split2u(float v0, float v1, uint32_t& hi, uint32_t& lo) {
    __nv_bfloat162 h = __floats2bfloat162_rn(v0, v1);
    float r0 = v0 - __bfloat162float(h.x);
    float r1 = v1 - __bfloat162float(h.y);
    __nv_bfloat162 l = __floats2bfloat162_rn(r0, r1);
    hi = *reinterpret_cast<uint32_t*>(&h);
    lo = *reinterpret_cast<uint32_t*>(&l);
}

// ---------------- presplit kernels ----------------
#define C4W (E * D * HID / 4)
#define C4X (NMAX * D / 4)

// W1 + X + scalar init (feeds ffn1; runs on main stream)
__global__ void split_w1x_init(const float* __restrict__ W1,
                               const float* __restrict__ x) {
    long long i = (long long)blockIdx.x * blockDim.x + threadIdx.x;
    if (i == 0) {
        g_lse2 = 0.0f;
#pragma unroll
        for (int e = 0; e < E; e++) { g_cnt[e] = 0; g_imp[e] = 0.0f; }
    }
    const float* src;
    __nv_bfloat16 *dhi, *dlo;
    long long j;
    if (i < C4W)                 { src = W1; dhi = g_W1hi; dlo = g_W1lo; j = i; }
    else if (i < C4W + C4X)      { src = x;  dhi = g_Xhi;  dlo = g_Xlo;  j = i - C4W; }
    else return;
    float4 v = ((const float4*)src)[j];
    uint2 h, l;
    split2u(v.x, v.y, h.x, l.x);
    split2u(v.z, v.w, h.y, l.y);
    ((uint2*)dhi)[j] = h;
    ((uint2*)dlo)[j] = l;
}

// W2 split (only needed by ffn2; runs on side stream, overlapped with ffn1)
__global__ void split_w2(const float* __restrict__ W2) {
    long long i = (long long)blockIdx.x * blockDim.x + threadIdx.x;
    if (i >= C4W) return;
    float4 v = ((const float4*)W2)[i];
    uint2 h, l;
    split2u(v.x, v.y, h.x, l.x);
    split2u(v.z, v.w, h.y, l.y);
    ((uint2*)g_W2hi)[i] = h;
    ((uint2*)g_W2lo)[i] = l;
}

// ---------------- router ----------------
__global__ void router_kernel(const float* __restrict__ x,
                              const float* __restrict__ Wr,
                              const float* __restrict__ br, int N) {
    int gwarp = (blockIdx.x * blockDim.x + threadIdx.x) >> 5;
    int lane  = threadIdx.x & 31;
    if (gwarp >= N) return;
    int t = gwarp;
    const float* xr = x + (size_t)t * D;

    float acc[E];
#pragma unroll
    for (int e = 0; e < E; e++) acc[e] = 0.0f;
    for (int d = lane; d < D; d += 32) {
        float xv = xr[d];
        const float4* w4 = (const float4*)(Wr + (size_t)d * E);
        float4 wa = w4[0], wb = w4[1];
        acc[0] += xv * wa.x; acc[1] += xv * wa.y;
        acc[2] += xv * wa.z; acc[3] += xv * wa.w;
        acc[4] += xv * wb.x; acc[5] += xv * wb.y;
        acc[6] += xv * wb.z; acc[7] += xv * wb.w;
    }
#pragma unroll
    for (int e = 0; e < E; e++) {
#pragma unroll
        for (int off = 16; off; off >>= 1)
            acc[e] += __shfl_down_sync(0xffffffffu, acc[e], off);
    }

    if (lane == 0) {
        float l[E];
#pragma unroll
        for (int e = 0; e < E; e++) l[e] = acc[e] + br[e];
        float m = l[0];
#pragma unroll
        for (int e = 1; e < E; e++) m = fmaxf(m, l[e]);
        float p[E]; float s = 0.0f;
#pragma unroll
        for (int e = 0; e < E; e++) { p[e] = expf(l[e] - m); s += p[e]; }
        float inv = 1.0f / s;
        float lse = m + logf(s);
        atomicAdd(&g_lse2, lse * lse);

        int i0 = 0, i1 = 0; float p0 = -1.0f, p1 = -1.0f;
#pragma unroll
        for (int e = 0; e < E; e++) {
            float pe = p[e] * inv;
            atomicAdd(&g_imp[e], pe);
            if (pe > p0)      { p1 = p0; i1 = i0; p0 = pe; i0 = e; }
            else if (pe > p1) { p1 = pe; i1 = e; }
        }
        float wsum = p0 + p1 + 1e-12f;
        float w0 = p0 / wsum, w1 = p1 / wsum;
        int pos0 = atomicAdd(&g_cnt[i0], 1);
        int pos1 = atomicAdd(&g_cnt[i1], 1);
        g_list[i0 * NMAX + pos0] = t;
        g_list[i1 * NMAX + pos1] = t;
        int t2 = t * 2;
        g_tok_e[t2]     = i0; g_tok_p[t2]     = pos0; g_tok_w[t2]     = w0;
        g_tok_e[t2 + 1] = i1; g_tok_p[t2 + 1] = pos1; g_tok_w[t2 + 1] = w1;
    }
}

__global__ void scan_kernel() {
    if (threadIdx.x == 0) {
        int o = 0;
        for (int e = 0; e < E; e++) { g_offs[e] = o; o += g_cnt[e]; }
    }
}

// ---------------- mma.sync GEMM ----------------
// Tile: 128(M) x 128(N), BK=32, split-bf16 (hi/lo), 3-MMA per term-pair.
// 256 threads = 8 warps, warp tile 32x64 (4 warps M x 2 warps N).
// 3-stage cp.async ring, ONE __syncthreads per chunk. 113.7KB smem -> 2 CTAs/SM.
#define A_LD_B   80      // A row pitch bytes (40 bf16)
#define B_LD_B   272     // B row pitch bytes (136 bf16)
#define A_REG_SZ 10240   // 128*80
#define B_REG_SZ 8704    // 32*272
#define STAGE_BYTES (2*A_REG_SZ + 2*B_REG_SZ)   // 37888
#define SMEM_TOTAL  (3 * STAGE_BYTES)           // 113664

template<int PHASE>
__global__ __launch_bounds__(256, 2) void ffn_mma(
    const __nv_bfloat16* __restrict__ Whi,
    const __nv_bfloat16* __restrict__ Wlo,
    const float* __restrict__ bias)
{
    constexpr int KDIM = (PHASE == 1) ? D : HID;
    constexpr int NDIM = (PHASE == 1) ? HID : D;
    constexpr int NCH  = KDIM / 32;

    int e = blockIdx.z;
    int n = g_cnt[e];
    int r0 = blockIdx.y * 128;
    if (r0 >= n) return;
    int c0 = blockIdx.x * 128;
    int base = g_offs[e];

    extern __shared__ char smem[];
    uint32_t sb = smem_u32(smem);
    int t = threadIdx.x;
    int lane = t & 31, wid = t >> 5;

    // ---- per-thread cp.async source/dst setup ----
    int arow0 = t >> 2;
    const char* asrc[2][2];   // [hl][rowhalf]
    uint32_t abytes[2];
#pragma unroll
    for (int half = 0; half < 2; half++) {
        int rowg = r0 + arow0 + 64 * half;
        bool valid = rowg < n;
        size_t off;
        if (PHASE == 1) {
            int tok = valid ? g_list[e * NMAX + rowg] : 0;
            off = (size_t)tok * D + (t & 3) * 8;
            asrc[0][half] = (const char*)(g_Xhi + off);
            asrc[1][half] = (const char*)(g_Xlo + off);
        } else {
            int rr = valid ? rowg : 0;
            off = (size_t)(base + rr) * HID + (t & 3) * 8;
            asrc[0][half] = (const char*)(g_Hhi + off);
            asrc[1][half] = (const char*)(g_Hlo + off);
        }
        abytes[half] = valid ? 16u : 0u;
    }
    uint32_t adst0 = (uint32_t)(arow0 * A_LD_B + (t & 3) * 16);
    uint32_t adst1 = adst0 + 64 * A_LD_B;

    int bk0 = t >> 4;
    size_t wbase = (size_t)e * KDIM * NDIM + (size_t)bk0 * NDIM + c0 + (t & 15) * 8;
    const char* bsrc_h0 = (const char*)(Whi + wbase);
    const char* bsrc_h1 = (const char*)(Whi + wbase + (size_t)16 * NDIM);
    const char* bsrc_l0 = (const char*)(Wlo + wbase);
    const char* bsrc_l1 = (const char*)(Wlo + wbase + (size_t)16 * NDIM);
    uint32_t bdst0 = (uint32_t)(bk0 * B_LD_B + (t & 15) * 16);
    uint32_t bdst1 = bdst0 + 16 * B_LD_B;

    auto issue = [&](int kc, int stage) {
        uint32_t s0 = sb + stage * STAGE_BYTES;
        size_t aoff = (size_t)kc * 64;                 // 32 bf16 per chunk
        size_t boff = (size_t)kc * 32 * NDIM * 2;      // bytes
        cpasync16(s0 + adst0,               asrc[0][0] + aoff, abytes[0]);
        cpasync16(s0 + adst1,               asrc[0][1] + aoff, abytes[1]);
        cpasync16(s0 + A_REG_SZ + adst0,    asrc[1][0] + aoff, abytes[0]);
        cpasync16(s0 + A_REG_SZ + adst1,    asrc[1][1] + aoff, abytes[1]);
        uint32_t bb = s0 + 2 * A_REG_SZ;
        cpasync16(bb + bdst0,              bsrc_h0 + boff, 16);
        cpasync16(bb + bdst1,              bsrc_h1 + boff, 16);
        cpasync16(bb + B_REG_SZ + bdst0,   bsrc_l0 + boff, 16);
        cpasync16(bb + B_REG_SZ + bdst1,   bsrc_l1 + boff, 16);
    };

    // ---- per-warp ldmatrix lane offsets ----
    int m0  = (wid & 3) * 32;
    int n0w = (wid >> 2) * 64;
    uint32_t a_lane = (uint32_t)((m0 + (lane & 15)) * A_LD_B + (lane >> 4) * 16);
    uint32_t b_lane = (uint32_t)(((lane & 7) + 8 * ((lane >> 3) & 1)) * B_LD_B
                                 + (n0w + 8 * (lane >> 4)) * 2);

    float acc[2][8][4];
#pragma unroll
    for (int mt = 0; mt < 2; mt++)
#pragma unroll
        for (int nt = 0; nt < 8; nt++)
#pragma unroll
            for (int q = 0; q < 4; q++) acc[mt][nt][q] = 0.0f;

    // 3-stage prologue: 2 chunks in flight
    issue(0, 0); CP_COMMIT();
    issue(1, 1); CP_COMMIT();

    for (int kc = 0; kc < NCH; kc++) {
        CP_WAITG1();                     // this thread's chunk kc landed
        __syncthreads();                 // all threads' chunk kc landed; all done reading (kc-1)%3

        uint32_t sA = sb + (kc % 3) * STAGE_BYTES;
        uint32_t sB = sA + 2 * A_REG_SZ;

#pragma unroll
        for (int ks = 0; ks < 2; ks++) {       // k sub-steps of 16
            uint32_t af[2][2][4];
#pragma unroll
            for (int hl = 0; hl < 2; hl++)
#pragma unroll
                for (int mt = 0; mt < 2; mt++)
                    ldsm4(af[hl][mt], sA + hl * A_REG_SZ + a_lane
                          + mt * 16 * A_LD_B + ks * 32);
#pragma unroll
            for (int g = 0; g < 4; g++) {      // n groups of 16 cols (2 nt each)
                uint32_t bh[4], bl[4];
                ldsm4t(bh, sB + b_lane + ks * 16 * B_LD_B + g * 32);
                ldsm4t(bl, sB + B_REG_SZ + b_lane + ks * 16 * B_LD_B + g * 32);
#pragma unroll
                for (int mt = 0; mt < 2; mt++) {
#pragma unroll
                    for (int sub = 0; sub < 2; sub++) {
                        float* a = acc[mt][g * 2 + sub];
                        mma_bf16(a, af[0][mt], &bh[sub * 2]);
                        mma_bf16(a, af[0][mt], &bl[sub * 2]);
                        mma_bf16(a, af[1][mt], &bh[sub * 2]);
                    }
                }
            }
        }

        if (kc + 2 < NCH) issue(kc + 2, (kc + 2) % 3);   // overwrites stage (kc-1)%3: safe past barrier
        CP_COMMIT();                                     // unconditional: keeps group count uniform
    }

    // ---- epilogue ----
    int lr = lane >> 2;
    int lc = (lane & 3) * 2;
#pragma unroll
    for (int mt = 0; mt < 2; mt++) {
#pragma unroll
        for (int nt = 0; nt < 8; nt++) {
            int col = c0 + n0w + nt * 8 + lc;
            float bz0 = bias[e * NDIM + col];
            float bz1 = bias[e * NDIM + col + 1];
            int ra = r0 + m0 + mt * 16 + lr;
            int rb = ra + 8;
            float* a = acc[mt][nt];
            if (PHASE == 1) {
                if (ra < n) {
                    float v0 = gelu_tanh(a[0] + bz0);
                    float v1 = gelu_tanh(a[1] + bz1);
                    uint32_t h, l; split2u(v0, v1, h, l);
                    size_t o = (size_t)(base + ra) * HID + col;
                    *(uint32_t*)(g_Hhi + o) = h;
                    *(uint32_t*)(g_Hlo + o) = l;
                }
                if (rb < n) {
                    float v0 = gelu_tanh(a[2] + bz0);
                    float v1 = gelu_tanh(a[3] + bz1);
                    uint32_t h, l; split2u(v0, v1, h, l);
                    size_t o = (size_t)(base + rb) * HID + col;
                    *(uint32_t*)(g_Hhi + o) = h;
                    *(uint32_t*)(g_Hlo + o) = l;
                }
            } else {
                if (ra < n)
                    *(float2*)(g_Y + (size_t)(base + ra) * D + col)
                        = make_float2(a[0] + bz0, a[1] + bz1);
                if (rb < n)
                    *(float2*)(g_Y + (size_t)(base + rb) * D + col)
                        = make_float2(a[2] + bz0, a[3] + bz1);
            }
        }
    }
}

// ---------------- combine + finalize ----------------
__global__ void combine_kernel(float* __restrict__ out) {
    int t = blockIdx.x;
    int t2 = t * 2;
    int e0 = g_tok_e[t2],     e1 = g_tok_e[t2 + 1];
    int r0 = g_offs[e0] + g_tok_p[t2];
    int r1 = g_offs[e1] + g_tok_p[t2 + 1];
    float w0 = g_tok_w[t2], w1 = g_tok_w[t2 + 1];

    int d = threadIdx.x * 4;
    float4 y0 = *(const float4*)(g_Y + (size_t)r0 * D + d);
    float4 y1 = *(const float4*)(g_Y + (size_t)r1 * D + d);
    float4 o;
    o.x = w0 * y0.x + w1 * y1.x;
    o.y = w0 * y0.y + w1 * y1.y;
    o.z = w0 * y0.z + w1 * y1.z;
    o.w = w0 * y0.w + w1 * y1.w;
    *(float4*)(out + (size_t)t * D + d) = o;
}

__global__ void finalize_kernel(float* __restrict__ out, int N, long long out_size) {
    if (threadIdx.x == 0) {
        float invN = 1.0f / (float)N;
        float z = g_lse2 * invN;
        float s = 0.0f;
        for (int e = 0; e < E; e++)
            s += (g_imp[e] * invN) * ((float)g_cnt[e] * invN);
        long long base = (long long)N * D;
        out[base]     = z;
        out[base + 1] = (float)E * s;
        for (long long i = base + 2; i < out_size; i++) out[i] = 0.0f;
    }
}

extern "C" void kernel_launch(void* const* d_in, const int* in_sizes, int n_in,
                              void* d_out, int out_size) {
    const float* x  = (const float*)d_in[0];
    const float* Wr = (const float*)d_in[1];
    const float* br = (const float*)d_in[2];
    const float* W1 = (const float*)d_in[3];
    const float* b1 = (const float*)d_in[4];
    const float* W2 = (const float*)d_in[5];
    const float* b2 = (const float*)d_in[6];
    float* out = (float*)d_out;

    int N = in_sizes[0] / D;  // 2048

    void *p_w1hi, *p_w1lo, *p_w2hi, *p_w2lo;
    cudaGetSymbolAddress(&p_w1hi, g_W1hi);
    cudaGetSymbolAddress(&p_w1lo, g_W1lo);
    cudaGetSymbolAddress(&p_w2hi, g_W2hi);
    cudaGetSymbolAddress(&p_w2lo, g_W2lo);

    cudaFuncSetAttribute(ffn_mma<1>, cudaFuncAttributeMaxDynamicSharedMemorySize, SMEM_TOTAL);
    cudaFuncSetAttribute(ffn_mma<2>, cudaFuncAttributeMaxDynamicSharedMemorySize, SMEM_TOTAL);

    // side stream + events for overlapping the W2 presplit with ffn1.
    // Created per call (not destroyed: destroying a capture-participating
    // stream before capture ends would invalidate the capture).
    cudaStream_t s2;
    cudaEvent_t evFork, evW2;
    cudaStreamCreateWithFlags(&s2, cudaStreamNonBlocking);
    cudaEventCreateWithFlags(&evFork, cudaEventDisableTiming);
    cudaEventCreateWithFlags(&evW2,  cudaEventDisableTiming);

    // fork: side stream runs split_w2 concurrently with main-stream work
    cudaEventRecord(evFork, 0);
    cudaStreamWaitEvent(s2, evFork, 0);
    split_w2<<<(C4W + 255) / 256, 256, 0, s2>>>(W2);
    cudaEventRecord(evW2, s2);

    // main stream: W1+X split, router, scan, ffn1
    {
        long long items = (long long)C4W + C4X;
        split_w1x_init<<<(int)((items + 255) / 256), 256>>>(W1, x);
    }
    {
        int warps_per_block = 8;
        int blocks = (N + warps_per_block - 1) / warps_per_block;
        router_kernel<<<blocks, warps_per_block * 32>>>(x, Wr, br, N);
    }
    scan_kernel<<<1, 1>>>();
    {
        dim3 grid(HID / 128, NMAX / 128, E);   // 32 x 16 x 8
        ffn_mma<1><<<grid, 256, SMEM_TOTAL>>>((const __nv_bfloat16*)p_w1hi,
                                              (const __nv_bfloat16*)p_w1lo, b1);
    }
    // join: ffn2 needs the W2 split
    cudaStreamWaitEvent(0, evW2, 0);
    {
        dim3 grid(D / 128, NMAX / 128, E);     // 8 x 16 x 8
        ffn_mma<2><<<grid, 256, SMEM_TOTAL>>>((const __nv_bfloat16*)p_w2hi,
                                              (const __nv_bfloat16*)p_w2lo, b2);
    }
    combine_kernel<<<N, 256>>>(out);
    finalize_kernel<<<1, 32>>>(out, N, (long long)out_size);
}

// round 12
// speedup vs baseline: 3.2763x; 1.0259x over previous
#include <cuda_runtime.h>
#include <cuda_bf16.h>
#include <math.h>
#include <stdint.h>

#define D    1024
#define E    8
#define HID  4096
#define NMAX 2048

// ---------------- device scratch (static globals: allowed) ----------------
__device__ __nv_bfloat16 g_Xhi[NMAX * D];
__device__ __nv_bfloat16 g_Xlo[NMAX * D];
__device__ __nv_bfloat16 g_W1hi[E * D * HID];
__device__ __nv_bfloat16 g_W1lo[E * D * HID];
__device__ __nv_bfloat16 g_W2hi[E * HID * D];
__device__ __nv_bfloat16 g_W2lo[E * HID * D];
__device__ __nv_bfloat16 g_Hhi[2 * NMAX * HID];
__device__ __nv_bfloat16 g_Hlo[2 * NMAX * HID];
__device__ int   g_cnt[E];
__device__ int   g_offs[E];
__device__ int   g_list[E * NMAX];   // packed-slot -> token
__device__ float g_wrow[E * NMAX];   // packed-slot -> combine weight
__device__ float g_imp[E];
__device__ float g_lse2;

// ---------------- helpers ----------------
__device__ __forceinline__ uint32_t smem_u32(const void* p) {
    uint32_t a;
    asm("{ .reg .u64 t; cvta.to.shared.u64 t, %1; cvt.u32.u64 %0, t; }"
        : "=r"(a) : "l"(p));
    return a;
}

__device__ __forceinline__ void cpasync16(uint32_t dst, const void* src, uint32_t bytes) {
    asm volatile("cp.async.cg.shared.global [%0], [%1], 16, %2;"
                 :: "r"(dst), "l"(src), "r"(bytes));
}
#define CP_COMMIT() asm volatile("cp.async.commit_group;")
#define CP_WAITG1() asm volatile("cp.async.wait_group 1;")

__device__ __forceinline__ void ldsm4(uint32_t* r, uint32_t addr) {
    asm volatile("ldmatrix.sync.aligned.m8n8.x4.shared.b16 {%0,%1,%2,%3}, [%4];"
                 : "=r"(r[0]), "=r"(r[1]), "=r"(r[2]), "=r"(r[3]) : "r"(addr));
}
__device__ __forceinline__ void ldsm4t(uint32_t* r, uint32_t addr) {
    asm volatile("ldmatrix.sync.aligned.m8n8.x4.trans.shared.b16 {%0,%1,%2,%3}, [%4];"
                 : "=r"(r[0]), "=r"(r[1]), "=r"(r[2]), "=r"(r[3]) : "r"(addr));
}
__device__ __forceinline__ void mma_bf16(float* c, const uint32_t* a, const uint32_t* b) {
    asm volatile(
        "mma.sync.aligned.m16n8k16.row.col.f32.bf16.bf16.f32 "
        "{%0,%1,%2,%3}, {%4,%5,%6,%7}, {%8,%9}, {%0,%1,%2,%3};"
        : "+f"(c[0]), "+f"(c[1]), "+f"(c[2]), "+f"(c[3])
        : "r"(a[0]), "r"(a[1]), "r"(a[2]), "r"(a[3]), "r"(b[0]), "r"(b[1]));
}

__device__ __forceinline__ float gelu_tanh(float v) {
    const float c = 0.7978845608028654f;
    float t = tanhf(c * (v + 0.044715f * v * v * v));
    return 0.5f * v * (1.0f + t);
}

__device__ __forceinline__ void split2u(float v0, float v1, uint32_t& hi, uint32_t& lo) {
    __nv_bfloat162 h = __floats2bfloat162_rn(v0, v1);
    float r0 = v0 - __bfloat162float(h.x);
    float r1 = v1 - __bfloat162float(h.y);
    __nv_bfloat162 l = __floats2bfloat162_rn(r0, r1);
    hi = *reinterpret_cast<uint32_t*>(&h);
    lo = *reinterpret_cast<uint32_t*>(&l);
}

// ---------------- presplit kernels ----------------
#define C4W (E * D * HID / 4)
#define C4X (NMAX * D / 4)

// W1 + X split (feeds ffn1; main stream)
__global__ void split_w1x(const float* __restrict__ W1,
                          const float* __restrict__ x) {
    long long i = (long long)blockIdx.x * blockDim.x + threadIdx.x;
    const float* src;
    __nv_bfloat16 *dhi, *dlo;
    long long j;
    if (i < C4W)            { src = W1; dhi = g_W1hi; dlo = g_W1lo; j = i; }
    else if (i < C4W + C4X) { src = x;  dhi = g_Xhi;  dlo = g_Xlo;  j = i - C4W; }
    else return;
    float4 v = ((const float4*)src)[j];
    uint2 h, l;
    split2u(v.x, v.y, h.x, l.x);
    split2u(v.z, v.w, h.y, l.y);
    ((uint2*)dhi)[j] = h;
    ((uint2*)dlo)[j] = l;
}

// W2 split (side stream, overlapped with ffn1)
__global__ void split_w2(const float* __restrict__ W2) {
    long long i = (long long)blockIdx.x * blockDim.x + threadIdx.x;
    if (i >= C4W) return;
    float4 v = ((const float4*)W2)[i];
    uint2 h, l;
    split2u(v.x, v.y, h.x, l.x);
    split2u(v.z, v.w, h.y, l.y);
    ((uint2*)g_W2hi)[i] = h;
    ((uint2*)g_W2lo)[i] = l;
}

// zero d_out accumulation region + scalar init (must precede router on s2)
__global__ void zero_out_init(float* __restrict__ out) {
    long long i = (long long)blockIdx.x * blockDim.x + threadIdx.x;
    if (i == 0) {
        g_lse2 = 0.0f;
#pragma unroll
        for (int e = 0; e < E; e++) { g_cnt[e] = 0; g_imp[e] = 0.0f; }
    }
    if (i < (long long)NMAX * D / 4)
        ((float4*)out)[i] = make_float4(0.f, 0.f, 0.f, 0.f);
}

// ---------------- router ----------------
__global__ void router_kernel(const float* __restrict__ x,
                              const float* __restrict__ Wr,
                              const float* __restrict__ br, int N) {
    int gwarp = (blockIdx.x * blockDim.x + threadIdx.x) >> 5;
    int lane  = threadIdx.x & 31;
    if (gwarp >= N) return;
    int t = gwarp;
    const float* xr = x + (size_t)t * D;

    float acc[E];
#pragma unroll
    for (int e = 0; e < E; e++) acc[e] = 0.0f;
    for (int d = lane; d < D; d += 32) {
        float xv = xr[d];
        const float4* w4 = (const float4*)(Wr + (size_t)d * E);
        float4 wa = w4[0], wb = w4[1];
        acc[0] += xv * wa.x; acc[1] += xv * wa.y;
        acc[2] += xv * wa.z; acc[3] += xv * wa.w;
        acc[4] += xv * wb.x; acc[5] += xv * wb.y;
        acc[6] += xv * wb.z; acc[7] += xv * wb.w;
    }
#pragma unroll
    for (int e = 0; e < E; e++) {
#pragma unroll
        for (int off = 16; off; off >>= 1)
            acc[e] += __shfl_down_sync(0xffffffffu, acc[e], off);
    }

    if (lane == 0) {
        float l[E];
#pragma unroll
        for (int e = 0; e < E; e++) l[e] = acc[e] + br[e];
        float m = l[0];
#pragma unroll
        for (int e = 1; e < E; e++) m = fmaxf(m, l[e]);
        float p[E]; float s = 0.0f;
#pragma unroll
        for (int e = 0; e < E; e++) { p[e] = expf(l[e] - m); s += p[e]; }
        float inv = 1.0f / s;
        float lse = m + logf(s);
        atomicAdd(&g_lse2, lse * lse);

        int i0 = 0, i1 = 0; float p0 = -1.0f, p1 = -1.0f;
#pragma unroll
        for (int e = 0; e < E; e++) {
            float pe = p[e] * inv;
            atomicAdd(&g_imp[e], pe);
            if (pe > p0)      { p1 = p0; i1 = i0; p0 = pe; i0 = e; }
            else if (pe > p1) { p1 = pe; i1 = e; }
        }
        float wsum = p0 + p1 + 1e-12f;
        float w0 = p0 / wsum, w1 = p1 / wsum;
        int pos0 = atomicAdd(&g_cnt[i0], 1);
        int pos1 = atomicAdd(&g_cnt[i1], 1);
        g_list[i0 * NMAX + pos0] = t;  g_wrow[i0 * NMAX + pos0] = w0;
        g_list[i1 * NMAX + pos1] = t;  g_wrow[i1 * NMAX + pos1] = w1;
    }
}

__global__ void scan_kernel() {
    if (threadIdx.x == 0) {
        int o = 0;
        for (int e = 0; e < E; e++) { g_offs[e] = o; o += g_cnt[e]; }
    }
}

// ---------------- mma.sync GEMM ----------------
// Tile: 128(M) x 128(N), BK=32, split-bf16 (hi/lo), 3-MMA per term-pair.
// 256 threads = 8 warps, warp tile 32x64 (4 warps M x 2 warps N).
// 3-stage cp.async ring, ONE __syncthreads per chunk. 113.7KB smem -> 2 CTAs/SM.
#define A_LD_B   80      // A row pitch bytes (40 bf16)
#define B_LD_B   272     // B row pitch bytes (136 bf16)
#define A_REG_SZ 10240   // 128*80
#define B_REG_SZ 8704    // 32*272
#define STAGE_BYTES (2*A_REG_SZ + 2*B_REG_SZ)   // 37888
#define SMEM_TOTAL  (3 * STAGE_BYTES)           // 113664

template<int PHASE>
__global__ __launch_bounds__(256, 2) void ffn_mma(
    const __nv_bfloat16* __restrict__ Whi,
    const __nv_bfloat16* __restrict__ Wlo,
    const float* __restrict__ bias,
    float* __restrict__ out)
{
    constexpr int KDIM = (PHASE == 1) ? D : HID;
    constexpr int NDIM = (PHASE == 1) ? HID : D;
    constexpr int NCH  = KDIM / 32;

    int e = blockIdx.z;
    int n = g_cnt[e];
    int r0 = blockIdx.y * 128;
    if (r0 >= n) return;
    int c0 = blockIdx.x * 128;
    int base = g_offs[e];

    extern __shared__ char smem[];
    uint32_t sb = smem_u32(smem);
    int t = threadIdx.x;
    int lane = t & 31, wid = t >> 5;

    // ---- per-thread cp.async source/dst setup ----
    int arow0 = t >> 2;
    const char* asrc[2][2];   // [hl][rowhalf]
    uint32_t abytes[2];
#pragma unroll
    for (int half = 0; half < 2; half++) {
        int rowg = r0 + arow0 + 64 * half;
        bool valid = rowg < n;
        size_t off;
        if (PHASE == 1) {
            int tok = valid ? g_list[e * NMAX + rowg] : 0;
            off = (size_t)tok * D + (t & 3) * 8;
            asrc[0][half] = (const char*)(g_Xhi + off);
            asrc[1][half] = (const char*)(g_Xlo + off);
        } else {
            int rr = valid ? rowg : 0;
            off = (size_t)(base + rr) * HID + (t & 3) * 8;
            asrc[0][half] = (const char*)(g_Hhi + off);
            asrc[1][half] = (const char*)(g_Hlo + off);
        }
        abytes[half] = valid ? 16u : 0u;
    }
    uint32_t adst0 = (uint32_t)(arow0 * A_LD_B + (t & 3) * 16);
    uint32_t adst1 = adst0 + 64 * A_LD_B;

    int bk0 = t >> 4;
    size_t wbase = (size_t)e * KDIM * NDIM + (size_t)bk0 * NDIM + c0 + (t & 15) * 8;
    const char* bsrc_h0 = (const char*)(Whi + wbase);
    const char* bsrc_h1 = (const char*)(Whi + wbase + (size_t)16 * NDIM);
    const char* bsrc_l0 = (const char*)(Wlo + wbase);
    const char* bsrc_l1 = (const char*)(Wlo + wbase + (size_t)16 * NDIM);
    uint32_t bdst0 = (uint32_t)(bk0 * B_LD_B + (t & 15) * 16);
    uint32_t bdst1 = bdst0 + 16 * B_LD_B;

    auto issue = [&](int kc, int stage) {
        uint32_t s0 = sb + stage * STAGE_BYTES;
        size_t aoff = (size_t)kc * 64;                 // 32 bf16 per chunk
        size_t boff = (size_t)kc * 32 * NDIM * 2;      // bytes
        cpasync16(s0 + adst0,               asrc[0][0] + aoff, abytes[0]);
        cpasync16(s0 + adst1,               asrc[0][1] + aoff, abytes[1]);
        cpasync16(s0 + A_REG_SZ + adst0,    asrc[1][0] + aoff, abytes[0]);
        cpasync16(s0 + A_REG_SZ + adst1,    asrc[1][1] + aoff, abytes[1]);
        uint32_t bb = s0 + 2 * A_REG_SZ;
        cpasync16(bb + bdst0,              bsrc_h0 + boff, 16);
        cpasync16(bb + bdst1,              bsrc_h1 + boff, 16);
        cpasync16(bb + B_REG_SZ + bdst0,   bsrc_l0 + boff, 16);
        cpasync16(bb + B_REG_SZ + bdst1,   bsrc_l1 + boff, 16);
    };

    // ---- per-warp ldmatrix lane offsets ----
    int m0  = (wid & 3) * 32;
    int n0w = (wid >> 2) * 64;
    uint32_t a_lane = (uint32_t)((m0 + (lane & 15)) * A_LD_B + (lane >> 4) * 16);
    uint32_t b_lane = (uint32_t)(((lane & 7) + 8 * ((lane >> 3) & 1)) * B_LD_B
                                 + (n0w + 8 * (lane >> 4)) * 2);

    float acc[2][8][4];
#pragma unroll
    for (int mt = 0; mt < 2; mt++)
#pragma unroll
        for (int nt = 0; nt < 8; nt++)
#pragma unroll
            for (int q = 0; q < 4; q++) acc[mt][nt][q] = 0.0f;

    // 3-stage prologue: 2 chunks in flight
    issue(0, 0); CP_COMMIT();
    issue(1, 1); CP_COMMIT();

    for (int kc = 0; kc < NCH; kc++) {
        CP_WAITG1();                     // this thread's chunk kc landed
        __syncthreads();                 // all threads' chunk kc landed; all done reading (kc-1)%3

        uint32_t sA = sb + (kc % 3) * STAGE_BYTES;
        uint32_t sB = sA + 2 * A_REG_SZ;

#pragma unroll
        for (int ks = 0; ks < 2; ks++) {       // k sub-steps of 16
            uint32_t af[2][2][4];
#pragma unroll
            for (int hl = 0; hl < 2; hl++)
#pragma unroll
                for (int mt = 0; mt < 2; mt++)
                    ldsm4(af[hl][mt], sA + hl * A_REG_SZ + a_lane
                          + mt * 16 * A_LD_B + ks * 32);
#pragma unroll
            for (int g = 0; g < 4; g++) {      // n groups of 16 cols (2 nt each)
                uint32_t bh[4], bl[4];
                ldsm4t(bh, sB + b_lane + ks * 16 * B_LD_B + g * 32);
                ldsm4t(bl, sB + B_REG_SZ + b_lane + ks * 16 * B_LD_B + g * 32);
#pragma unroll
                for (int mt = 0; mt < 2; mt++) {
#pragma unroll
                    for (int sub = 0; sub < 2; sub++) {
                        float* a = acc[mt][g * 2 + sub];
                        mma_bf16(a, af[0][mt], &bh[sub * 2]);
                        mma_bf16(a, af[0][mt], &bl[sub * 2]);
                        mma_bf16(a, af[1][mt], &bh[sub * 2]);
                    }
                }
            }
        }

        if (kc + 2 < NCH) issue(kc + 2, (kc + 2) % 3);   // overwrites stage (kc-1)%3: safe past barrier
        CP_COMMIT();                                     // unconditional: keeps group count uniform
    }

    // ---- epilogue ----
    int lr = lane >> 2;
    int lc = (lane & 3) * 2;

    if (PHASE == 1) {
#pragma unroll
        for (int mt = 0; mt < 2; mt++) {
#pragma unroll
            for (int nt = 0; nt < 8; nt++) {
                int col = c0 + n0w + nt * 8 + lc;
                float bz0 = bias[e * NDIM + col];
                float bz1 = bias[e * NDIM + col + 1];
                int ra = r0 + m0 + mt * 16 + lr;
                int rb = ra + 8;
                float* a = acc[mt][nt];
                if (ra < n) {
                    float v0 = gelu_tanh(a[0] + bz0);
                    float v1 = gelu_tanh(a[1] + bz1);
                    uint32_t h, l; split2u(v0, v1, h, l);
                    size_t o = (size_t)(base + ra) * HID + col;
                    *(uint32_t*)(g_Hhi + o) = h;
                    *(uint32_t*)(g_Hlo + o) = l;
                }
                if (rb < n) {
                    float v0 = gelu_tanh(a[2] + bz0);
                    float v1 = gelu_tanh(a[3] + bz1);
                    uint32_t h, l; split2u(v0, v1, h, l);
                    size_t o = (size_t)(base + rb) * HID + col;
                    *(uint32_t*)(g_Hhi + o) = h;
                    *(uint32_t*)(g_Hlo + o) = l;
                }
            }
        }
    } else {
        // fused combine: out[token, col] += w * (acc + bias)
#pragma unroll
        for (int mt = 0; mt < 2; mt++) {
            int ra = r0 + m0 + mt * 16 + lr;
            int rb = ra + 8;
            int tokA = 0, tokB = 0; float wA = 0.f, wB = 0.f;
            if (ra < n) { tokA = g_list[e * NMAX + ra]; wA = g_wrow[e * NMAX + ra]; }
            if (rb < n) { tokB = g_list[e * NMAX + rb]; wB = g_wrow[e * NMAX + rb]; }
#pragma unroll
            for (int nt = 0; nt < 8; nt++) {
                int col = c0 + n0w + nt * 8 + lc;
                float bz0 = bias[e * NDIM + col];
                float bz1 = bias[e * NDIM + col + 1];
                float* a = acc[mt][nt];
                if (ra < n) {
                    atomicAdd(&out[(size_t)tokA * D + col],     wA * (a[0] + bz0));
                    atomicAdd(&out[(size_t)tokA * D + col + 1], wA * (a[1] + bz1));
                }
                if (rb < n) {
                    atomicAdd(&out[(size_t)tokB * D + col],     wB * (a[2] + bz0));
                    atomicAdd(&out[(size_t)tokB * D + col + 1], wB * (a[3] + bz1));
                }
            }
        }
    }
}

// ---------------- finalize ----------------
__global__ void finalize_kernel(float* __restrict__ out, int N, long long out_size) {
    if (threadIdx.x == 0) {
        float invN = 1.0f / (float)N;
        float z = g_lse2 * invN;
        float s = 0.0f;
        for (int e = 0; e < E; e++)
            s += (g_imp[e] * invN) * ((float)g_cnt[e] * invN);
        long long base = (long long)N * D;
        out[base]     = z;
        out[base + 1] = (float)E * s;
        for (long long i = base + 2; i < out_size; i++) out[i] = 0.0f;
    }
}

extern "C" void kernel_launch(void* const* d_in, const int* in_sizes, int n_in,
                              void* d_out, int out_size) {
    const float* x  = (const float*)d_in[0];
    const float* Wr = (const float*)d_in[1];
    const float* br = (const float*)d_in[2];
    const float* W1 = (const float*)d_in[3];
    const float* b1 = (const float*)d_in[4];
    const float* W2 = (const float*)d_in[5];
    const float* b2 = (const float*)d_in[6];
    float* out = (float*)d_out;

    int N = in_sizes[0] / D;  // 2048

    void *p_w1hi, *p_w1lo, *p_w2hi, *p_w2lo;
    cudaGetSymbolAddress(&p_w1hi, g_W1hi);
    cudaGetSymbolAddress(&p_w1lo, g_W1lo);
    cudaGetSymbolAddress(&p_w2hi, g_W2hi);
    cudaGetSymbolAddress(&p_w2lo, g_W2lo);

    cudaFuncSetAttribute(ffn_mma<1>, cudaFuncAttributeMaxDynamicSharedMemorySize, SMEM_TOTAL);
    cudaFuncSetAttribute(ffn_mma<2>, cudaFuncAttributeMaxDynamicSharedMemorySize, SMEM_TOTAL);

    // side stream + events (created per call; not destroyed — capture-safe)
    cudaStream_t s2;
    cudaEvent_t evFork, evRoute, evW2;
    cudaStreamCreateWithFlags(&s2, cudaStreamNonBlocking);
    cudaEventCreateWithFlags(&evFork,  cudaEventDisableTiming);
    cudaEventCreateWithFlags(&evRoute, cudaEventDisableTiming);
    cudaEventCreateWithFlags(&evW2,    cudaEventDisableTiming);

    // fork
    cudaEventRecord(evFork, 0);
    cudaStreamWaitEvent(s2, evFork, 0);

    // ---- side stream: init+zero, router, scan, then W2 split ----
    {
        long long items = (long long)NMAX * D / 4;
        zero_out_init<<<(int)((items + 255) / 256), 256, 0, s2>>>(out);
    }
    {
        int warps_per_block = 8;
        int blocks = (N + warps_per_block - 1) / warps_per_block;
        router_kernel<<<blocks, warps_per_block * 32, 0, s2>>>(x, Wr, br, N);
    }
    scan_kernel<<<1, 1, 0, s2>>>();
    cudaEventRecord(evRoute, s2);
    split_w2<<<(C4W + 255) / 256, 256, 0, s2>>>(W2);
    cudaEventRecord(evW2, s2);

    // ---- main stream: W1+X split (concurrent with router), then GEMMs ----
    {
        long long items = (long long)C4W + C4X;
        split_w1x<<<(int)((items + 255) / 256), 256>>>(W1, x);
    }
    cudaStreamWaitEvent(0, evRoute, 0);   // ffn1 needs router results
    {
        dim3 grid(HID / 128, NMAX / 128, E);   // 32 x 16 x 8
        ffn_mma<1><<<grid, 256, SMEM_TOTAL>>>((const __nv_bfloat16*)p_w1hi,
                                              (const __nv_bfloat16*)p_w1lo, b1, out);
    }
    cudaStreamWaitEvent(0, evW2, 0);      // ffn2 needs W2 split + zeroed out
    {
        dim3 grid(D / 128, NMAX / 128, E);     // 8 x 16 x 8
        ffn_mma<2><<<grid, 256, SMEM_TOTAL>>>((const __nv_bfloat16*)p_w2hi,
                                              (const __nv_bfloat16*)p_w2lo, b2, out);
    }
    finalize_kernel<<<1, 32>>>(out, N, (long long)out_size);
}